// round 5
// baseline (speedup 1.0000x reference)
#include <cuda_runtime.h>
#include <cuda_bf16.h>

#define NUM_GRAPHS 256
#define EDGE_DIM   128
#define GLOBAL_DIM 256
#define LN_EPS     1e-5f

// Scratch (allocation-free rule: __device__ globals)
__device__ float g_sums[NUM_GRAPHS * EDGE_DIM];
__device__ float g_counts[NUM_GRAPHS];

__global__ void zero_kernel() {
    int i = blockIdx.x * blockDim.x + threadIdx.x;
    if (i < NUM_GRAPHS * EDGE_DIM) g_sums[i] = 0.0f;
    if (i < NUM_GRAPHS)            g_counts[i] = 0.0f;
}

// One warp per contiguous chunk of edges. Lane l owns float4 columns [4l, 4l+4).
// Fast path (single segment in chunk): no per-edge batch reads, one atomic flush.
__global__ void __launch_bounds__(256) segsum_kernel(
    const float4* __restrict__ edge4,   // [n_edges, 32] float4
    const int* __restrict__ batch,      // [n_edges] int32, sorted
    int n_edges, int chunk)
{
    int warp  = (blockIdx.x * blockDim.x + threadIdx.x) >> 5;
    int lane  = threadIdx.x & 31;
    long long e0 = (long long)warp * chunk;
    long long e1 = e0 + chunk;
    if (e1 > n_edges) e1 = n_edges;
    if (e0 >= e1) return;

    int seg_first = batch[e0];
    int seg_last  = batch[e1 - 1];

    if (seg_first == seg_last) {
        // ---- fast path: whole chunk belongs to one graph ----
        float4 s = make_float4(0.f, 0.f, 0.f, 0.f);
        const float4* p = edge4 + e0 * 32 + lane;
        long long n = e1 - e0;
        long long e = 0;
        #pragma unroll 4
        for (; e + 4 <= n; e += 4) {
            float4 v0 = p[(e + 0) * 32];
            float4 v1 = p[(e + 1) * 32];
            float4 v2 = p[(e + 2) * 32];
            float4 v3 = p[(e + 3) * 32];
            s.x += v0.x + v1.x + v2.x + v3.x;
            s.y += v0.y + v1.y + v2.y + v3.y;
            s.z += v0.z + v1.z + v2.z + v3.z;
            s.w += v0.w + v1.w + v2.w + v3.w;
        }
        for (; e < n; e++) {
            float4 v = p[e * 32];
            s.x += v.x; s.y += v.y; s.z += v.z; s.w += v.w;
        }
        float* dst = &g_sums[seg_first * EDGE_DIM + lane * 4];
        atomicAdd(dst + 0, s.x);
        atomicAdd(dst + 1, s.y);
        atomicAdd(dst + 2, s.z);
        atomicAdd(dst + 3, s.w);
        if (lane == 0) atomicAdd(&g_counts[seg_first], (float)n);
    } else {
        // ---- slow path: chunk crosses >=1 segment boundary ----
        int   cur = seg_first;
        float cnt = 0.0f;
        float4 s = make_float4(0.f, 0.f, 0.f, 0.f);
        for (long long e = e0; e < e1; e++) {
            int seg = batch[e];   // broadcast load (same addr across warp)
            if (seg != cur) {
                float* dst = &g_sums[cur * EDGE_DIM + lane * 4];
                atomicAdd(dst + 0, s.x);
                atomicAdd(dst + 1, s.y);
                atomicAdd(dst + 2, s.z);
                atomicAdd(dst + 3, s.w);
                if (lane == 0) atomicAdd(&g_counts[cur], cnt);
                s = make_float4(0.f, 0.f, 0.f, 0.f);
                cnt = 0.0f;
                cur = seg;
            }
            float4 v = edge4[e * 32 + lane];
            s.x += v.x; s.y += v.y; s.z += v.z; s.w += v.w;
            cnt += 1.0f;
        }
        float* dst = &g_sums[cur * EDGE_DIM + lane * 4];
        atomicAdd(dst + 0, s.x);
        atomicAdd(dst + 1, s.y);
        atomicAdd(dst + 2, s.z);
        atomicAdd(dst + 3, s.w);
        if (lane == 0) atomicAdd(&g_counts[cur], cnt);
    }
}

// One block (256 threads) per graph: mean -> linear -> LayerNorm (two-pass).
__global__ void __launch_bounds__(GLOBAL_DIM) fuse_kernel(
    const float* __restrict__ W,    // [EDGE_DIM, GLOBAL_DIM]
    const float* __restrict__ b,    // [GLOBAL_DIM]
    const float* __restrict__ ln_w, // [GLOBAL_DIM]
    const float* __restrict__ ln_b, // [GLOBAL_DIM]
    float* __restrict__ out)        // [NUM_GRAPHS, GLOBAL_DIM]
{
    __shared__ float u_s[EDGE_DIM];
    __shared__ float red[16];
    __shared__ float bc[2];

    int g = blockIdx.x;
    int t = threadIdx.x;

    if (t < EDGE_DIM) {
        float c = fmaxf(g_counts[g], 1.0f);
        u_s[t] = g_sums[g * EDGE_DIM + t] / c;
    }
    __syncthreads();

    float acc = b[t];
    #pragma unroll 8
    for (int k = 0; k < EDGE_DIM; k++)
        acc = fmaf(u_s[k], W[k * GLOBAL_DIM + t], acc);

    int wid = t >> 5, lane = t & 31;

    // pass 1: mean
    float sum = acc;
    #pragma unroll
    for (int o = 16; o; o >>= 1) sum += __shfl_xor_sync(0xffffffffu, sum, o);
    if (lane == 0) red[wid] = sum;
    __syncthreads();
    if (t == 0) {
        float S = 0.f;
        #pragma unroll
        for (int w = 0; w < 8; w++) S += red[w];
        bc[0] = S / (float)GLOBAL_DIM;
    }
    __syncthreads();
    float mu = bc[0];

    // pass 2: variance
    float d = acc - mu;
    float sq = d * d;
    #pragma unroll
    for (int o = 16; o; o >>= 1) sq += __shfl_xor_sync(0xffffffffu, sq, o);
    if (lane == 0) red[wid] = sq;
    __syncthreads();
    if (t == 0) {
        float Q = 0.f;
        #pragma unroll
        for (int w = 0; w < 8; w++) Q += red[w];
        bc[1] = rsqrtf(Q / (float)GLOBAL_DIM + LN_EPS);
    }
    __syncthreads();
    float inv = bc[1];

    out[g * GLOBAL_DIM + t] = d * inv * ln_w[t] + ln_b[t];
}

extern "C" void kernel_launch(void* const* d_in, const int* in_sizes, int n_in,
                              void* d_out, int out_size) {
    const float* edge_attr = (const float*)d_in[0];
    const int*   batch     = (const int*)d_in[1];
    const float* W         = (const float*)d_in[2];
    const float* b         = (const float*)d_in[3];
    const float* ln_w      = (const float*)d_in[4];
    const float* ln_b      = (const float*)d_in[5];
    float*       out       = (float*)d_out;

    int n_edges = in_sizes[1];

    zero_kernel<<<(NUM_GRAPHS * EDGE_DIM + 255) / 256, 256>>>();

    const int blocks = 1184;                 // 148 SMs x 8 CTAs
    const int warps  = blocks * (256 / 32);  // 9472
    int chunk = (n_edges + warps - 1) / warps;
    if (chunk < 1) chunk = 1;
    segsum_kernel<<<blocks, 256>>>((const float4*)edge_attr, batch, n_edges, chunk);

    fuse_kernel<<<NUM_GRAPHS, 256>>>(W, b, ln_w, ln_b, out);
}

// round 6
// speedup vs baseline: 1.1587x; 1.1587x over previous
#include <cuda_runtime.h>
#include <cuda_bf16.h>

#define NUM_GRAPHS 256
#define EDGE_DIM   128
#define GLOBAL_DIM 256
#define LN_EPS     1e-5f

// Scratch (allocation-free rule: __device__ globals).
// Zero at module load; fuse_kernel re-zeros after use so graph replays stay clean.
__device__ float g_sums[NUM_GRAPHS * EDGE_DIM];
__device__ float g_counts[NUM_GRAPHS];

// One warp per contiguous chunk of ~423 edges. Lane l owns float4 columns [4l, 4l+4).
// Per segment-run inside the chunk: run end found in O(log chunk) broadcast loads
// (zero extra loads for single-segment chunks), then an unrolled streaming loop.
__global__ void __launch_bounds__(256) segsum_kernel(
    const float4* __restrict__ edge4,   // [n_edges, 32] float4
    const int* __restrict__ batch,      // [n_edges] int32, sorted
    int n_edges, int chunk)
{
    int warp  = (blockIdx.x * blockDim.x + threadIdx.x) >> 5;
    int lane  = threadIdx.x & 31;
    long long e0 = (long long)warp * chunk;
    long long e1 = e0 + chunk;
    if (e1 > n_edges) e1 = n_edges;
    if (e0 >= e1) return;

    int seg_last = batch[e1 - 1];

    long long e = e0;
    while (e < e1) {
        int seg = batch[e];
        long long end;
        if (seg == seg_last) {
            end = e1;                       // common case: rest of chunk is one run
        } else {
            long long lo = e, hi = e1 - 1;  // batch[lo]==seg, batch[hi]!=seg
            while (hi - lo > 1) {
                long long mid = (lo + hi) >> 1;
                if (batch[mid] == seg) lo = mid; else hi = mid;
            }
            end = hi;
        }

        float4 a0 = make_float4(0.f, 0.f, 0.f, 0.f);
        float4 a1 = make_float4(0.f, 0.f, 0.f, 0.f);
        const float4* p = edge4 + e * 32 + lane;
        long long n = end - e;
        long long i = 0;
        #pragma unroll 1
        for (; i + 8 <= n; i += 8) {
            float4 v0 = __ldcs(p + (i + 0) * 32);
            float4 v1 = __ldcs(p + (i + 1) * 32);
            float4 v2 = __ldcs(p + (i + 2) * 32);
            float4 v3 = __ldcs(p + (i + 3) * 32);
            float4 v4 = __ldcs(p + (i + 4) * 32);
            float4 v5 = __ldcs(p + (i + 5) * 32);
            float4 v6 = __ldcs(p + (i + 6) * 32);
            float4 v7 = __ldcs(p + (i + 7) * 32);
            a0.x += v0.x + v1.x + v2.x + v3.x;
            a0.y += v0.y + v1.y + v2.y + v3.y;
            a0.z += v0.z + v1.z + v2.z + v3.z;
            a0.w += v0.w + v1.w + v2.w + v3.w;
            a1.x += v4.x + v5.x + v6.x + v7.x;
            a1.y += v4.y + v5.y + v6.y + v7.y;
            a1.z += v4.z + v5.z + v6.z + v7.z;
            a1.w += v4.w + v5.w + v6.w + v7.w;
        }
        for (; i < n; i++) {
            float4 v = __ldcs(p + i * 32);
            a0.x += v.x; a0.y += v.y; a0.z += v.z; a0.w += v.w;
        }
        a0.x += a1.x; a0.y += a1.y; a0.z += a1.z; a0.w += a1.w;

        float* dst = &g_sums[seg * EDGE_DIM + lane * 4];
        atomicAdd(dst + 0, a0.x);
        atomicAdd(dst + 1, a0.y);
        atomicAdd(dst + 2, a0.z);
        atomicAdd(dst + 3, a0.w);
        if (lane == 0) atomicAdd(&g_counts[seg], (float)n);

        e = end;
    }
}

// One block (256 threads) per graph: mean -> linear -> LayerNorm (two-pass).
// Also resets the scratch globals for the next graph replay.
__global__ void __launch_bounds__(GLOBAL_DIM) fuse_kernel(
    const float* __restrict__ W,    // [EDGE_DIM, GLOBAL_DIM]
    const float* __restrict__ b,    // [GLOBAL_DIM]
    const float* __restrict__ ln_w, // [GLOBAL_DIM]
    const float* __restrict__ ln_b, // [GLOBAL_DIM]
    float* __restrict__ out)        // [NUM_GRAPHS, GLOBAL_DIM]
{
    __shared__ float u_s[EDGE_DIM];
    __shared__ float red[16];
    __shared__ float bc[2];

    int g = blockIdx.x;
    int t = threadIdx.x;

    if (t < EDGE_DIM) {
        float c = fmaxf(g_counts[g], 1.0f);
        u_s[t] = g_sums[g * EDGE_DIM + t] / c;
    }
    __syncthreads();

    // reset scratch for the next replay (after all reads above)
    if (t < EDGE_DIM) g_sums[g * EDGE_DIM + t] = 0.0f;
    if (t == 0)       g_counts[g] = 0.0f;

    float acc = b[t];
    #pragma unroll 8
    for (int k = 0; k < EDGE_DIM; k++)
        acc = fmaf(u_s[k], W[k * GLOBAL_DIM + t], acc);

    int wid = t >> 5, lane = t & 31;

    // pass 1: mean
    float sum = acc;
    #pragma unroll
    for (int o = 16; o; o >>= 1) sum += __shfl_xor_sync(0xffffffffu, sum, o);
    if (lane == 0) red[wid] = sum;
    __syncthreads();
    if (t == 0) {
        float S = 0.f;
        #pragma unroll
        for (int w = 0; w < 8; w++) S += red[w];
        bc[0] = S / (float)GLOBAL_DIM;
    }
    __syncthreads();
    float mu = bc[0];

    // pass 2: variance
    float d = acc - mu;
    float sq = d * d;
    #pragma unroll
    for (int o = 16; o; o >>= 1) sq += __shfl_xor_sync(0xffffffffu, sq, o);
    if (lane == 0) red[wid] = sq;
    __syncthreads();
    if (t == 0) {
        float Q = 0.f;
        #pragma unroll
        for (int w = 0; w < 8; w++) Q += red[w];
        bc[1] = rsqrtf(Q / (float)GLOBAL_DIM + LN_EPS);
    }
    __syncthreads();
    float inv = bc[1];

    out[g * GLOBAL_DIM + t] = d * inv * ln_w[t] + ln_b[t];
}

extern "C" void kernel_launch(void* const* d_in, const int* in_sizes, int n_in,
                              void* d_out, int out_size) {
    const float* edge_attr = (const float*)d_in[0];
    const int*   batch     = (const int*)d_in[1];
    const float* W         = (const float*)d_in[2];
    const float* b         = (const float*)d_in[3];
    const float* ln_w      = (const float*)d_in[4];
    const float* ln_b      = (const float*)d_in[5];
    float*       out       = (float*)d_out;

    int n_edges = in_sizes[1];

    // Single wave: 4 CTAs/SM resident at any plausible register count.
    const int blocks = 592;                  // 148 SMs x 4 CTAs
    const int warps  = blocks * (256 / 32);  // 4736
    int chunk = (n_edges + warps - 1) / warps;
    if (chunk < 1) chunk = 1;
    segsum_kernel<<<blocks, 256>>>((const float4*)edge_attr, batch, n_edges, chunk);

    fuse_kernel<<<NUM_GRAPHS, 256>>>(W, b, ln_w, ln_b, out);
}

// round 7
// speedup vs baseline: 1.1723x; 1.0117x over previous
#include <cuda_runtime.h>
#include <cuda_bf16.h>

#define NUM_GRAPHS 256
#define EDGE_DIM   128
#define GLOBAL_DIM 256
#define LN_EPS     1e-5f

// Scratch (allocation-free rule: __device__ globals).
// Zero at module load; fuse_kernel re-zeros after use so graph replays stay clean.
__device__ float g_sums[NUM_GRAPHS * EDGE_DIM];
__device__ float g_counts[NUM_GRAPHS];

// One warp per contiguous chunk of ~423 edges. Lane l owns float4 columns [4l, 4l+4).
// Per segment-run inside the chunk: run end found in O(log chunk) broadcast loads
// (zero extra loads for single-segment chunks), then an unrolled streaming loop.
__global__ void __launch_bounds__(256) segsum_kernel(
    const float4* __restrict__ edge4,   // [n_edges, 32] float4
    const int* __restrict__ batch,      // [n_edges] int32, sorted
    int n_edges, int chunk)
{
    int warp  = (blockIdx.x * blockDim.x + threadIdx.x) >> 5;
    int lane  = threadIdx.x & 31;
    long long e0 = (long long)warp * chunk;
    long long e1 = e0 + chunk;
    if (e1 > n_edges) e1 = n_edges;
    if (e0 >= e1) return;

    int seg_last = batch[e1 - 1];

    long long e = e0;
    while (e < e1) {
        int seg = batch[e];
        long long end;
        if (seg == seg_last) {
            end = e1;                       // common case: rest of chunk is one run
        } else {
            long long lo = e, hi = e1 - 1;  // batch[lo]==seg, batch[hi]!=seg
            while (hi - lo > 1) {
                long long mid = (lo + hi) >> 1;
                if (batch[mid] == seg) lo = mid; else hi = mid;
            }
            end = hi;
        }

        float4 a0 = make_float4(0.f, 0.f, 0.f, 0.f);
        float4 a1 = make_float4(0.f, 0.f, 0.f, 0.f);
        const float4* p = edge4 + e * 32 + lane;
        long long n = end - e;
        long long i = 0;
        #pragma unroll 1
        for (; i + 8 <= n; i += 8) {
            float4 v0 = __ldcs(p + (i + 0) * 32);
            float4 v1 = __ldcs(p + (i + 1) * 32);
            float4 v2 = __ldcs(p + (i + 2) * 32);
            float4 v3 = __ldcs(p + (i + 3) * 32);
            float4 v4 = __ldcs(p + (i + 4) * 32);
            float4 v5 = __ldcs(p + (i + 5) * 32);
            float4 v6 = __ldcs(p + (i + 6) * 32);
            float4 v7 = __ldcs(p + (i + 7) * 32);
            a0.x += v0.x + v1.x + v2.x + v3.x;
            a0.y += v0.y + v1.y + v2.y + v3.y;
            a0.z += v0.z + v1.z + v2.z + v3.z;
            a0.w += v0.w + v1.w + v2.w + v3.w;
            a1.x += v4.x + v5.x + v6.x + v7.x;
            a1.y += v4.y + v5.y + v6.y + v7.y;
            a1.z += v4.z + v5.z + v6.z + v7.z;
            a1.w += v4.w + v5.w + v6.w + v7.w;
        }
        for (; i < n; i++) {
            float4 v = __ldcs(p + i * 32);
            a0.x += v.x; a0.y += v.y; a0.z += v.z; a0.w += v.w;
        }
        a0.x += a1.x; a0.y += a1.y; a0.z += a1.z; a0.w += a1.w;

        float* dst = &g_sums[seg * EDGE_DIM + lane * 4];
        atomicAdd(dst + 0, a0.x);
        atomicAdd(dst + 1, a0.y);
        atomicAdd(dst + 2, a0.z);
        atomicAdd(dst + 3, a0.w);
        if (lane == 0) atomicAdd(&g_counts[seg], (float)n);

        e = end;
    }
}

// One block (512 threads) per graph. k-dim split 2-way: threads (c, c+256)
// each cover 64 k's of the 128-deep dot product (halves the load-latency
// chain; full unroll maximizes loads in flight). Then two-pass LayerNorm.
// Also resets the scratch globals for the next graph replay.
__global__ void __launch_bounds__(512) fuse_kernel(
    const float* __restrict__ W,    // [EDGE_DIM, GLOBAL_DIM]
    const float* __restrict__ b,    // [GLOBAL_DIM]
    const float* __restrict__ ln_w, // [GLOBAL_DIM]
    const float* __restrict__ ln_b, // [GLOBAL_DIM]
    float* __restrict__ out)        // [NUM_GRAPHS, GLOBAL_DIM]
{
    __shared__ float u_s[EDGE_DIM];
    __shared__ float part[GLOBAL_DIM];
    __shared__ float red[16];
    __shared__ float bc[2];

    int g = blockIdx.x;
    int t = threadIdx.x;
    int col  = t & (GLOBAL_DIM - 1);
    int half = t >> 8;               // 0 or 1

    if (t < EDGE_DIM) {
        float c = fmaxf(g_counts[g], 1.0f);
        u_s[t] = g_sums[g * EDGE_DIM + t] / c;
    }
    __syncthreads();

    // reset scratch for the next replay (after all reads above)
    if (t < EDGE_DIM) g_sums[g * EDGE_DIM + t] = 0.0f;
    if (t == 0)       g_counts[g] = 0.0f;

    // 64-deep partial dot product, fully unrolled for MLP
    const float* Wp = W + (half * 64) * GLOBAL_DIM + col;
    const float* up = u_s + half * 64;
    float acc = 0.0f;
    #pragma unroll
    for (int k = 0; k < 64; k++)
        acc = fmaf(up[k], Wp[k * GLOBAL_DIM], acc);

    if (half == 1) part[col] = acc;
    __syncthreads();

    float a = 0.0f;
    if (half == 0) a = acc + part[col] + b[col];

    int wid = t >> 5, lane = t & 31;

    // pass 1: mean (upper half contributes zeros; divide by GLOBAL_DIM)
    float sum = a;
    #pragma unroll
    for (int o = 16; o; o >>= 1) sum += __shfl_xor_sync(0xffffffffu, sum, o);
    if (lane == 0) red[wid] = sum;
    __syncthreads();
    if (t == 0) {
        float S = 0.f;
        #pragma unroll
        for (int w = 0; w < 16; w++) S += red[w];
        bc[0] = S / (float)GLOBAL_DIM;
    }
    __syncthreads();
    float mu = bc[0];

    // pass 2: variance (guard upper half to contribute zero)
    float d  = a - mu;
    float sq = (half == 0) ? d * d : 0.0f;
    #pragma unroll
    for (int o = 16; o; o >>= 1) sq += __shfl_xor_sync(0xffffffffu, sq, o);
    if (lane == 0) red[wid] = sq;
    __syncthreads();
    if (t == 0) {
        float Q = 0.f;
        #pragma unroll
        for (int w = 0; w < 16; w++) Q += red[w];
        bc[1] = rsqrtf(Q / (float)GLOBAL_DIM + LN_EPS);
    }
    __syncthreads();
    float inv = bc[1];

    if (half == 0)
        out[g * GLOBAL_DIM + col] = d * inv * ln_w[col] + ln_b[col];
}

extern "C" void kernel_launch(void* const* d_in, const int* in_sizes, int n_in,
                              void* d_out, int out_size) {
    const float* edge_attr = (const float*)d_in[0];
    const int*   batch     = (const int*)d_in[1];
    const float* W         = (const float*)d_in[2];
    const float* b         = (const float*)d_in[3];
    const float* ln_w      = (const float*)d_in[4];
    const float* ln_b      = (const float*)d_in[5];
    float*       out       = (float*)d_out;

    int n_edges = in_sizes[1];

    // Single wave: 4 CTAs/SM resident at any plausible register count.
    const int blocks = 592;                  // 148 SMs x 4 CTAs
    const int warps  = blocks * (256 / 32);  // 4736
    int chunk = (n_edges + warps - 1) / warps;
    if (chunk < 1) chunk = 1;
    segsum_kernel<<<blocks, 256>>>((const float4*)edge_attr, batch, n_edges, chunk);

    fuse_kernel<<<NUM_GRAPHS, 512>>>(W, b, ln_w, ln_b, out);
}

// round 9
// speedup vs baseline: 1.1994x; 1.0231x over previous
#include <cuda_runtime.h>
#include <cuda_bf16.h>

#define NUM_GRAPHS 256
#define EDGE_DIM   128
#define GLOBAL_DIM 256
#define LN_EPS     1e-5f

// Scratch (allocation-free rule: __device__ globals).
// Zero at module load; fuse_kernel re-zeros after use so graph replays stay clean.
__device__ float g_sums[NUM_GRAPHS * EDGE_DIM];
__device__ float g_counts[NUM_GRAPHS];

// One warp per contiguous chunk of ~423 edges. Lane l owns float4 columns [4l, 4l+4).
// Per segment-run inside the chunk: run end found in O(log chunk) broadcast loads
// (zero extra loads for single-segment chunks), then an unrolled streaming loop.
// At 7.16 TB/s this is at the HBM streaming ceiling — do not touch.
__global__ void __launch_bounds__(256) segsum_kernel(
    const float4* __restrict__ edge4,   // [n_edges, 32] float4
    const int* __restrict__ batch,      // [n_edges] int32, sorted
    int n_edges, int chunk)
{
    int warp  = (blockIdx.x * blockDim.x + threadIdx.x) >> 5;
    int lane  = threadIdx.x & 31;
    long long e0 = (long long)warp * chunk;
    long long e1 = e0 + chunk;
    if (e1 > n_edges) e1 = n_edges;
    if (e0 >= e1) return;

    int seg_last = batch[e1 - 1];

    long long e = e0;
    while (e < e1) {
        int seg = batch[e];
        long long end;
        if (seg == seg_last) {
            end = e1;                       // common case: rest of chunk is one run
        } else {
            long long lo = e, hi = e1 - 1;  // batch[lo]==seg, batch[hi]!=seg
            while (hi - lo > 1) {
                long long mid = (lo + hi) >> 1;
                if (batch[mid] == seg) lo = mid; else hi = mid;
            }
            end = hi;
        }

        float4 a0 = make_float4(0.f, 0.f, 0.f, 0.f);
        float4 a1 = make_float4(0.f, 0.f, 0.f, 0.f);
        const float4* p = edge4 + e * 32 + lane;
        long long n = end - e;
        long long i = 0;
        #pragma unroll 1
        for (; i + 8 <= n; i += 8) {
            float4 v0 = __ldcs(p + (i + 0) * 32);
            float4 v1 = __ldcs(p + (i + 1) * 32);
            float4 v2 = __ldcs(p + (i + 2) * 32);
            float4 v3 = __ldcs(p + (i + 3) * 32);
            float4 v4 = __ldcs(p + (i + 4) * 32);
            float4 v5 = __ldcs(p + (i + 5) * 32);
            float4 v6 = __ldcs(p + (i + 6) * 32);
            float4 v7 = __ldcs(p + (i + 7) * 32);
            a0.x += v0.x + v1.x + v2.x + v3.x;
            a0.y += v0.y + v1.y + v2.y + v3.y;
            a0.z += v0.z + v1.z + v2.z + v3.z;
            a0.w += v0.w + v1.w + v2.w + v3.w;
            a1.x += v4.x + v5.x + v6.x + v7.x;
            a1.y += v4.y + v5.y + v6.y + v7.y;
            a1.z += v4.z + v5.z + v6.z + v7.z;
            a1.w += v4.w + v5.w + v6.w + v7.w;
        }
        for (; i < n; i++) {
            float4 v = __ldcs(p + i * 32);
            a0.x += v.x; a0.y += v.y; a0.z += v.z; a0.w += v.w;
        }
        a0.x += a1.x; a0.y += a1.y; a0.z += a1.z; a0.w += a1.w;

        float* dst = &g_sums[seg * EDGE_DIM + lane * 4];
        atomicAdd(dst + 0, a0.x);
        atomicAdd(dst + 1, a0.y);
        atomicAdd(dst + 2, a0.z);
        atomicAdd(dst + 3, a0.w);
        if (lane == 0) atomicAdd(&g_counts[seg], (float)n);

        e = end;
    }
}

// One block (512 threads) per graph. 8-way k-split with float4 W loads:
// thread (q = t>>6, c4 = t&63) accumulates k in [16q, 16q+16) for columns
// [4*c4, 4*c4+4) — 16 independent LDG.128s into 4 accumulators (high MLP,
// short chains). Partials combine through smem, then two-pass LayerNorm.
// Also resets the scratch globals for the next graph replay.
__global__ void __launch_bounds__(512, 2) fuse_kernel(
    const float* __restrict__ W,    // [EDGE_DIM, GLOBAL_DIM]
    const float* __restrict__ b,    // [GLOBAL_DIM]
    const float* __restrict__ ln_w, // [GLOBAL_DIM]
    const float* __restrict__ ln_b, // [GLOBAL_DIM]
    float* __restrict__ out)        // [NUM_GRAPHS, GLOBAL_DIM]
{
    __shared__ float u_s[EDGE_DIM];
    __shared__ float part_s[8 * GLOBAL_DIM];   // 8 KB: [q][col]
    __shared__ float red[16];
    __shared__ float bc[2];

    int g = blockIdx.x;
    int t = threadIdx.x;

    if (t < EDGE_DIM) {
        float c = fmaxf(g_counts[g], 1.0f);
        u_s[t] = g_sums[g * EDGE_DIM + t] / c;
    }
    __syncthreads();

    // reset scratch for the next replay (after all reads above)
    if (t < EDGE_DIM) g_sums[g * EDGE_DIM + t] = 0.0f;
    if (t == 0)       g_counts[g] = 0.0f;

    int c4 = t & 63;   // float4 column group: cols [4*c4, 4*c4+4)
    int q  = t >> 6;   // k-group: k in [16q, 16q+16)

    const float4* W4 = (const float4*)W;        // [EDGE_DIM][64]
    const float4* wp = W4 + (q * 16) * 64 + c4;
    const float*  uq = u_s + q * 16;

    float4 acc = make_float4(0.f, 0.f, 0.f, 0.f);
    #pragma unroll
    for (int k = 0; k < 16; k++) {
        float4 w = wp[k * 64];
        float  u = uq[k];
        acc.x = fmaf(u, w.x, acc.x);
        acc.y = fmaf(u, w.y, acc.y);
        acc.z = fmaf(u, w.z, acc.z);
        acc.w = fmaf(u, w.w, acc.w);
    }
    // part_s[q][4*c4 .. 4*c4+3] = acc  (float4 store, conflict-free)
    ((float4*)part_s)[q * 64 + c4] = acc;
    __syncthreads();

    int half = t >> 8;           // 0 or 1
    float a = 0.0f;
    if (half == 0) {
        float s = b[t];
        #pragma unroll
        for (int qq = 0; qq < 8; qq++)
            s += part_s[qq * GLOBAL_DIM + t];   // stride-256 across qq, conflict-free per warp
        a = s;
    }

    int wid = t >> 5, lane = t & 31;

    // pass 1: mean (upper half contributes zeros; divide by GLOBAL_DIM)
    float sum = a;
    #pragma unroll
    for (int o = 16; o; o >>= 1) sum += __shfl_xor_sync(0xffffffffu, sum, o);
    if (lane == 0) red[wid] = sum;
    __syncthreads();
    if (t == 0) {
        float S = 0.f;
        #pragma unroll
        for (int w = 0; w < 16; w++) S += red[w];
        bc[0] = S / (float)GLOBAL_DIM;
    }
    __syncthreads();
    float mu = bc[0];

    // pass 2: variance (guard upper half to contribute zero)
    float d  = a - mu;
    float sq = (half == 0) ? d * d : 0.0f;
    #pragma unroll
    for (int o = 16; o; o >>= 1) sq += __shfl_xor_sync(0xffffffffu, sq, o);
    if (lane == 0) red[wid] = sq;
    __syncthreads();
    if (t == 0) {
        float Q = 0.f;
        #pragma unroll
        for (int w = 0; w < 16; w++) Q += red[w];
        bc[1] = rsqrtf(Q / (float)GLOBAL_DIM + LN_EPS);
    }
    __syncthreads();
    float inv = bc[1];

    if (half == 0)
        out[g * GLOBAL_DIM + t] = d * inv * ln_w[t] + ln_b[t];
}

extern "C" void kernel_launch(void* const* d_in, const int* in_sizes, int n_in,
                              void* d_out, int out_size) {
    const float* edge_attr = (const float*)d_in[0];
    const int*   batch     = (const int*)d_in[1];
    const float* W         = (const float*)d_in[2];
    const float* b         = (const float*)d_in[3];
    const float* ln_w      = (const float*)d_in[4];
    const float* ln_b      = (const float*)d_in[5];
    float*       out       = (float*)d_out;

    int n_edges = in_sizes[1];

    // Single wave: 4 CTAs/SM resident at any plausible register count.
    const int blocks = 592;                  // 148 SMs x 4 CTAs
    const int warps  = blocks * (256 / 32);  // 4736
    int chunk = (n_edges + warps - 1) / warps;
    if (chunk < 1) chunk = 1;
    segsum_kernel<<<blocks, 256>>>((const float4*)edge_attr, batch, n_edges, chunk);

    fuse_kernel<<<NUM_GRAPHS, 512>>>(W, b, ln_w, ln_b, out);
}